// round 6
// baseline (speedup 1.0000x reference)
#include <cuda_runtime.h>
#include <cuda_bf16.h>
#include <cstdint>

// Problem constants (dataset fixed: N=50000, E=800000, IN=128, H=64, C=16)
#define MAXN 50016
#define H 64
#define IN_F 128
#define C_OUT 16

// Scratch (device globals; 16B aligned)
__device__ __align__(16) int   g_degi[MAXN];
__device__ __align__(16) float g_dinv[MAXN];
__device__ __align__(16) float g_hs1[MAXN * H];
__device__ __align__(16) float g_acc1[MAXN * H];
__device__ __align__(16) float g_hs2[MAXN * H];
__device__ __align__(16) float g_acc2[MAXN * H];
__device__ __align__(16) float g_A[MAXN * H];
__device__ __align__(16) float g_B[MAXN * H];

typedef unsigned long long ull;

// packed f32x2 FMA: acc = a*b + acc (elementwise on (lo,hi) pairs)
__device__ __forceinline__ void ffma2(ull& acc, ull a, ull b) {
    asm("fma.rn.f32x2 %0, %1, %2, %0;" : "+l"(acc) : "l"(a), "l"(b));
}
__device__ __forceinline__ float2 unpk(ull v) {
    float2 r;
    asm("mov.b64 {%0, %1}, %2;" : "=f"(r.x), "=f"(r.y) : "l"(v));
    return r;
}

// ---------------- degree count (int atomics; g_degi pre-zeroed by memset)
__global__ void count_kernel(const int* __restrict__ dst, int E) {
    int e = blockIdx.x * blockDim.x + threadIdx.x;
    if (e < E) atomicAdd(&g_degi[dst[e]], 1);
}

// =====================================================================
// Tiled GEMM kernels, f32x2 inner loop.
// M-tile=64, N-tile=64, 256 threads, 4x4 microtile.
// Ad[m][2k] holds A duplicated as (a,a) pairs -> LDS.64 broadcast.
// Ws[k][n] rows give natural (w_j, w_j+1) pairs via ulonglong2.
// =====================================================================

#define GEMM_MAIN_LOOP()                                                        \
    _Pragma("unroll 8")                                                         \
    for (int kk = 0; kk < 64; kk++) {                                           \
        ulonglong2 w2 = *reinterpret_cast<const ulonglong2*>(&Ws[kk][tx * 4]);  \
        ull a0 = *reinterpret_cast<const ull*>(&Ad[ty * 4 + 0][2 * kk]);        \
        ull a1 = *reinterpret_cast<const ull*>(&Ad[ty * 4 + 1][2 * kk]);        \
        ull a2 = *reinterpret_cast<const ull*>(&Ad[ty * 4 + 2][2 * kk]);        \
        ull a3 = *reinterpret_cast<const ull*>(&Ad[ty * 4 + 3][2 * kk]);        \
        ffma2(acc[0][0], a0, w2.x); ffma2(acc[0][1], a0, w2.y);                 \
        ffma2(acc[1][0], a1, w2.x); ffma2(acc[1][1], a1, w2.y);                 \
        ffma2(acc[2][0], a2, w2.x); ffma2(acc[2][1], a2, w2.y);                 \
        ffma2(acc[3][0], a3, w2.x); ffma2(acc[3][1], a3, w2.y);                 \
    }

__device__ __forceinline__ void stage_dup(float* dst, float4 v) {
    // store (v.x,v.x,v.y,v.y) and (v.z,v.z,v.w,v.w)
    *reinterpret_cast<float4*>(dst)     = make_float4(v.x, v.x, v.y, v.y);
    *reinterpret_cast<float4*>(dst + 4) = make_float4(v.z, v.z, v.w, v.w);
}

// conv1: hs1 = (x @ W1) * dinv ; acc1 = hs1 (self-loop seed); also writes g_dinv
__global__ __launch_bounds__(256) void gemm1_tiled(
    const float* __restrict__ x, const float* __restrict__ W1, int N) {
    __shared__ float Ad[64][136];   // [m][2k] duplicated
    __shared__ float Ws[64][68];    // [k][n]
    const int tx = threadIdx.x, ty = threadIdx.y;
    const int t = ty * 16 + tx;
    const int lm = t >> 4;
    const int lk4 = (t & 15) * 4;
    const int m0 = blockIdx.x * 64;

    ull acc[4][2];
#pragma unroll
    for (int i = 0; i < 4; i++) { acc[i][0] = 0ull; acc[i][1] = 0ull; }

    for (int k0 = 0; k0 < IN_F; k0 += 64) {
        __syncthreads();
#pragma unroll
        for (int i = 0; i < 4; i++) {
            int m = lm + 16 * i;
            int gm = m0 + m;
            float4 v = make_float4(0.f, 0.f, 0.f, 0.f);
            if (gm < N) v = *reinterpret_cast<const float4*>(x + (size_t)gm * IN_F + k0 + lk4);
            stage_dup(&Ad[m][2 * lk4], v);
            int k = lm + 16 * i;
            float4 w = *reinterpret_cast<const float4*>(W1 + (size_t)(k0 + k) * H + lk4);
            *reinterpret_cast<float4*>(&Ws[k][lk4]) = w;
        }
        __syncthreads();
        GEMM_MAIN_LOOP()
    }

#pragma unroll
    for (int i = 0; i < 4; i++) {
        int gm = m0 + ty * 4 + i;
        if (gm < N) {
            float di = rsqrtf((float)(g_degi[gm] + 1));  // +1 self loop
            if (tx == 0) g_dinv[gm] = di;
            float2 p0 = unpk(acc[i][0]);
            float2 p1 = unpk(acc[i][1]);
            float4 r = make_float4(p0.x * di, p0.y * di, p1.x * di, p1.y * di);
            *reinterpret_cast<float4*>(&g_hs1[(size_t)gm * H + tx * 4]) = r;
            *reinterpret_cast<float4*>(&g_acc1[(size_t)gm * H + tx * 4]) = r;
        }
    }
}

// conv2: h1 = relu(acc1*dinv + b1); hs2 = (h1 @ W2) * dinv; acc2 = hs2 (K=64)
__global__ __launch_bounds__(256) void gemm2_tiled(
    const float* __restrict__ W2, const float* __restrict__ b1, int N) {
    __shared__ float Ad[64][136];
    __shared__ float Ws[64][68];
    const int tx = threadIdx.x, ty = threadIdx.y;
    const int t = ty * 16 + tx;
    const int lm = t >> 4;
    const int lk4 = (t & 15) * 4;
    const int m0 = blockIdx.x * 64;

    float4 bb = *reinterpret_cast<const float4*>(b1 + lk4);
#pragma unroll
    for (int i = 0; i < 4; i++) {
        int m = lm + 16 * i;
        int gm = m0 + m;
        float4 v = make_float4(0.f, 0.f, 0.f, 0.f);
        if (gm < N) {
            float di = g_dinv[gm];
            float4 a = *reinterpret_cast<const float4*>(&g_acc1[(size_t)gm * H + lk4]);
            v.x = fmaxf(a.x * di + bb.x, 0.f);
            v.y = fmaxf(a.y * di + bb.y, 0.f);
            v.z = fmaxf(a.z * di + bb.z, 0.f);
            v.w = fmaxf(a.w * di + bb.w, 0.f);
        }
        stage_dup(&Ad[m][2 * lk4], v);
        int k = lm + 16 * i;
        float4 w = *reinterpret_cast<const float4*>(W2 + (size_t)k * H + lk4);
        *reinterpret_cast<float4*>(&Ws[k][lk4]) = w;
    }
    __syncthreads();

    ull acc[4][2];
#pragma unroll
    for (int i = 0; i < 4; i++) { acc[i][0] = 0ull; acc[i][1] = 0ull; }

    GEMM_MAIN_LOOP()

#pragma unroll
    for (int i = 0; i < 4; i++) {
        int gm = m0 + ty * 4 + i;
        if (gm < N) {
            float di = g_dinv[gm];
            float2 p0 = unpk(acc[i][0]);
            float2 p1 = unpk(acc[i][1]);
            float4 r = make_float4(p0.x * di, p0.y * di, p1.x * di, p1.y * di);
            *reinterpret_cast<float4*>(&g_hs2[(size_t)gm * H + tx * 4]) = r;
            *reinterpret_cast<float4*>(&g_acc2[(size_t)gm * H + tx * 4]) = r;
        }
    }
}

// node MLP precompute: h2 = relu(acc2*dinv + b2)
// half=0: g_A = h2 @ Wm1[0:64] + bm1 ; half=1: g_B = h2 @ Wm1[64:128]
__global__ __launch_bounds__(256) void gemm3_tiled(
    const float* __restrict__ Wm1, const float* __restrict__ b2,
    const float* __restrict__ bm1, int N) {
    __shared__ float Ad[64][136];
    __shared__ float Ws[64][68];
    const int tx = threadIdx.x, ty = threadIdx.y;
    const int t = ty * 16 + tx;
    const int lm = t >> 4;
    const int lk4 = (t & 15) * 4;
    const int m0 = blockIdx.x * 64;
    const int half = blockIdx.y;

    float4 bb = *reinterpret_cast<const float4*>(b2 + lk4);
#pragma unroll
    for (int i = 0; i < 4; i++) {
        int m = lm + 16 * i;
        int gm = m0 + m;
        float4 v = make_float4(0.f, 0.f, 0.f, 0.f);
        if (gm < N) {
            float di = g_dinv[gm];
            float4 a = *reinterpret_cast<const float4*>(&g_acc2[(size_t)gm * H + lk4]);
            v.x = fmaxf(a.x * di + bb.x, 0.f);
            v.y = fmaxf(a.y * di + bb.y, 0.f);
            v.z = fmaxf(a.z * di + bb.z, 0.f);
            v.w = fmaxf(a.w * di + bb.w, 0.f);
        }
        stage_dup(&Ad[m][2 * lk4], v);
        int k = lm + 16 * i;
        float4 w = *reinterpret_cast<const float4*>(Wm1 + (size_t)(half * H + k) * H + lk4);
        *reinterpret_cast<float4*>(&Ws[k][lk4]) = w;
    }
    __syncthreads();

    ull acc[4][2];
#pragma unroll
    for (int i = 0; i < 4; i++) { acc[i][0] = 0ull; acc[i][1] = 0ull; }

    GEMM_MAIN_LOOP()

    float4 badd = make_float4(0.f, 0.f, 0.f, 0.f);
    if (half == 0) badd = *reinterpret_cast<const float4*>(bm1 + tx * 4);
    float* outbuf = (half == 0) ? g_A : g_B;
#pragma unroll
    for (int i = 0; i < 4; i++) {
        int gm = m0 + ty * 4 + i;
        if (gm < N) {
            float2 p0 = unpk(acc[i][0]);
            float2 p1 = unpk(acc[i][1]);
            float4 r = make_float4(p0.x + badd.x, p0.y + badd.y,
                                   p1.x + badd.z, p1.y + badd.w);
            *reinterpret_cast<float4*>(&outbuf[(size_t)gm * H + tx * 4]) = r;
        }
    }
}

// ---------------- scatter: acc[dst] += hs[src]  (16 threads/edge, red.v4)
__global__ void scatter_kernel(const int* __restrict__ src, const int* __restrict__ dst,
                               const float* __restrict__ hs, float* __restrict__ acc, int E) {
    int t = blockIdx.x * blockDim.x + threadIdx.x;
    int e = t >> 4;
    if (e >= E) return;
    int c = (t & 15) << 2;
    int s = src[e], d = dst[e];
    float4 v = *reinterpret_cast<const float4*>(hs + (size_t)s * H + c);
    float* p = acc + (size_t)d * H + c;
    asm volatile("red.global.add.v4.f32 [%0], {%1, %2, %3, %4};"
                 :: "l"(p), "f"(v.x), "f"(v.y), "f"(v.z), "f"(v.w) : "memory");
}

// ---------------- edge MLP: out[e] = relu(A[src]+B[dst]) @ Wm2 + bm2
__global__ void edge_kernel(const int* __restrict__ src, const int* __restrict__ dst,
                            const float* __restrict__ Wm2, const float* __restrict__ bm2,
                            float* __restrict__ out, int E) {
    __shared__ float Ws[H * C_OUT];
    __shared__ float bs[C_OUT];
    int tid = threadIdx.x;
    for (int i = tid; i < H * C_OUT; i += blockDim.x) Ws[i] = Wm2[i];
    if (tid < C_OUT) bs[tid] = bm2[tid];
    __syncthreads();

    int e = blockIdx.x * blockDim.x + tid;
    if (e >= E) return;
    int s = src[e], d = dst[e];
    const float4* Ap = reinterpret_cast<const float4*>(g_A + (size_t)s * H);
    const float4* Bp = reinterpret_cast<const float4*>(g_B + (size_t)d * H);

    float acc[C_OUT];
#pragma unroll
    for (int c = 0; c < C_OUT; c++) acc[c] = bs[c];

#pragma unroll
    for (int q = 0; q < H / 4; q++) {
        float4 a4 = Ap[q];
        float4 b4 = Bp[q];
        float z0 = fmaxf(a4.x + b4.x, 0.f);
        float z1 = fmaxf(a4.y + b4.y, 0.f);
        float z2 = fmaxf(a4.z + b4.z, 0.f);
        float z3 = fmaxf(a4.w + b4.w, 0.f);
        int k = q * 4;
        const float4* w0 = reinterpret_cast<const float4*>(Ws + (k + 0) * C_OUT);
        const float4* w1 = reinterpret_cast<const float4*>(Ws + (k + 1) * C_OUT);
        const float4* w2 = reinterpret_cast<const float4*>(Ws + (k + 2) * C_OUT);
        const float4* w3 = reinterpret_cast<const float4*>(Ws + (k + 3) * C_OUT);
#pragma unroll
        for (int cq = 0; cq < 4; cq++) {
            float4 r0 = w0[cq], r1 = w1[cq], r2 = w2[cq], r3 = w3[cq];
            acc[cq * 4 + 0] += z0 * r0.x + z1 * r1.x + z2 * r2.x + z3 * r3.x;
            acc[cq * 4 + 1] += z0 * r0.y + z1 * r1.y + z2 * r2.y + z3 * r3.y;
            acc[cq * 4 + 2] += z0 * r0.z + z1 * r1.z + z2 * r2.z + z3 * r3.z;
            acc[cq * 4 + 3] += z0 * r0.w + z1 * r1.w + z2 * r2.w + z3 * r3.w;
        }
    }

    float4* op = reinterpret_cast<float4*>(out + (size_t)e * C_OUT);
#pragma unroll
    for (int c = 0; c < 4; c++)
        op[c] = make_float4(acc[c * 4 + 0], acc[c * 4 + 1], acc[c * 4 + 2], acc[c * 4 + 3]);
}

extern "C" void kernel_launch(void* const* d_in, const int* in_sizes, int n_in,
                              void* d_out, int out_size) {
    const float* x    = (const float*)d_in[0];
    const int*   ei   = (const int*)d_in[1];
    const float* W1   = (const float*)d_in[2];
    const float* b1   = (const float*)d_in[3];
    const float* W2   = (const float*)d_in[4];
    const float* b2   = (const float*)d_in[5];
    const float* Wm1  = (const float*)d_in[6];
    const float* bm1  = (const float*)d_in[7];
    const float* Wm2  = (const float*)d_in[8];
    const float* bm2  = (const float*)d_in[9];
    float* out = (float*)d_out;

    int N = in_sizes[0] / IN_F;
    int E = in_sizes[1] / 2;
    const int* src = ei;
    const int* dst = ei + E;

    int*   degi; cudaGetSymbolAddress((void**)&degi, g_degi);
    float* hs1;  cudaGetSymbolAddress((void**)&hs1,  g_hs1);
    float* acc1; cudaGetSymbolAddress((void**)&acc1, g_acc1);
    float* hs2;  cudaGetSymbolAddress((void**)&hs2,  g_hs2);
    float* acc2; cudaGetSymbolAddress((void**)&acc2, g_acc2);

    int blocks_m = (N + 63) / 64;

    // degrees
    cudaMemsetAsync(degi, 0, (size_t)N * sizeof(int));
    count_kernel<<<(E + 255) / 256, 256>>>(dst, E);

    // conv1 (dinv computed + persisted in epilogue)
    gemm1_tiled<<<blocks_m, dim3(16, 16)>>>(x, W1, N);
    {
        long long tot = (long long)E * 16;
        scatter_kernel<<<(int)((tot + 255) / 256), 256>>>(src, dst, hs1, acc1, E);
    }

    // conv2
    gemm2_tiled<<<blocks_m, dim3(16, 16)>>>(W2, b1, N);
    {
        long long tot = (long long)E * 16;
        scatter_kernel<<<(int)((tot + 255) / 256), 256>>>(src, dst, hs2, acc2, E);
    }

    // node-side MLP precompute
    gemm3_tiled<<<dim3(blocks_m, 2), dim3(16, 16)>>>(Wm1, b2, bm1, N);

    // edge MLP
    edge_kernel<<<(E + 255) / 256, 256>>>(src, dst, Wm2, bm2, out, E);
}

// round 7
// speedup vs baseline: 1.1090x; 1.1090x over previous
#include <cuda_runtime.h>
#include <cuda_bf16.h>
#include <cstdint>

// Problem constants (dataset fixed: N=50000, E=800000, IN=128, H=64, C=16)
#define MAXN 50016
#define H 64
#define IN_F 128
#define C_OUT 16

// Scratch (device globals; 16B aligned)
__device__ __align__(16) int   g_degi[MAXN];
__device__ __align__(16) float g_dinv[MAXN];
__device__ __align__(16) float g_hs1[MAXN * H];
__device__ __align__(16) float g_acc1[MAXN * H];
__device__ __align__(16) float g_hs2[MAXN * H];
__device__ __align__(16) float g_acc2[MAXN * H];
__device__ __align__(16) float g_A[MAXN * H];
__device__ __align__(16) float g_B[MAXN * H];

typedef unsigned long long ull;

__device__ __forceinline__ void ffma2(ull& acc, ull a, ull b) {
    asm("fma.rn.f32x2 %0, %1, %2, %0;" : "+l"(acc) : "l"(a), "l"(b));
}
__device__ __forceinline__ ull pk2(float a, float b) {
    ull r;
    asm("mov.b64 %0, {%1, %2};" : "=l"(r) : "f"(a), "f"(b));
    return r;
}
__device__ __forceinline__ float2 unpk(ull v) {
    float2 r;
    asm("mov.b64 {%0, %1}, %2;" : "=f"(r.x), "=f"(r.y) : "l"(v));
    return r;
}

// ---------------- degree count (int atomics; g_degi pre-zeroed by memset)
__global__ void count_kernel(const int* __restrict__ dst, int E) {
    int e = blockIdx.x * blockDim.x + threadIdx.x;
    if (e < E) atomicAdd(&g_degi[dst[e]], 1);
}

// =====================================================================
// Tiled GEMM kernels (R2 proven form): M=64, N=64, 256 thr, 4x4 microtile
// =====================================================================

// conv1: hs1 = (x @ W1) * dinv ; acc1 = hs1 (self-loop seed); writes g_dinv
__global__ __launch_bounds__(256) void gemm1_tiled(
    const float* __restrict__ x, const float* __restrict__ W1, int N) {
    __shared__ float As[64][68];
    __shared__ float Ws[64][68];
    const int tx = threadIdx.x, ty = threadIdx.y;
    const int t = ty * 16 + tx;
    const int lm = t >> 4;
    const int lk4 = (t & 15) * 4;
    const int m0 = blockIdx.x * 64;

    float acc[4][4];
#pragma unroll
    for (int i = 0; i < 4; i++)
#pragma unroll
        for (int j = 0; j < 4; j++) acc[i][j] = 0.f;

    for (int k0 = 0; k0 < IN_F; k0 += 64) {
        __syncthreads();
#pragma unroll
        for (int i = 0; i < 4; i++) {
            int m = lm + 16 * i;
            int gm = m0 + m;
            float4 v = make_float4(0.f, 0.f, 0.f, 0.f);
            if (gm < N) v = *reinterpret_cast<const float4*>(x + (size_t)gm * IN_F + k0 + lk4);
            *reinterpret_cast<float4*>(&As[m][lk4]) = v;
            int k = lm + 16 * i;
            float4 w = *reinterpret_cast<const float4*>(W1 + (size_t)(k0 + k) * H + lk4);
            *reinterpret_cast<float4*>(&Ws[k][lk4]) = w;
        }
        __syncthreads();
#pragma unroll 8
        for (int kk = 0; kk < 64; kk++) {
            float4 b4 = *reinterpret_cast<const float4*>(&Ws[kk][tx * 4]);
            float a0 = As[ty * 4 + 0][kk];
            float a1 = As[ty * 4 + 1][kk];
            float a2 = As[ty * 4 + 2][kk];
            float a3 = As[ty * 4 + 3][kk];
            acc[0][0] += a0 * b4.x; acc[0][1] += a0 * b4.y; acc[0][2] += a0 * b4.z; acc[0][3] += a0 * b4.w;
            acc[1][0] += a1 * b4.x; acc[1][1] += a1 * b4.y; acc[1][2] += a1 * b4.z; acc[1][3] += a1 * b4.w;
            acc[2][0] += a2 * b4.x; acc[2][1] += a2 * b4.y; acc[2][2] += a2 * b4.z; acc[2][3] += a2 * b4.w;
            acc[3][0] += a3 * b4.x; acc[3][1] += a3 * b4.y; acc[3][2] += a3 * b4.z; acc[3][3] += a3 * b4.w;
        }
    }

#pragma unroll
    for (int i = 0; i < 4; i++) {
        int gm = m0 + ty * 4 + i;
        if (gm < N) {
            float di = rsqrtf((float)(g_degi[gm] + 1));  // +1 self loop
            if (tx == 0) g_dinv[gm] = di;
            float4 r = make_float4(acc[i][0] * di, acc[i][1] * di, acc[i][2] * di, acc[i][3] * di);
            *reinterpret_cast<float4*>(&g_hs1[(size_t)gm * H + tx * 4]) = r;
            *reinterpret_cast<float4*>(&g_acc1[(size_t)gm * H + tx * 4]) = r;
        }
    }
}

// conv2: h1 = relu(acc1*dinv + b1); hs2 = (h1 @ W2) * dinv; acc2 = hs2 (K=64)
__global__ __launch_bounds__(256) void gemm2_tiled(
    const float* __restrict__ W2, const float* __restrict__ b1, int N) {
    __shared__ float As[64][68];
    __shared__ float Ws[64][68];
    const int tx = threadIdx.x, ty = threadIdx.y;
    const int t = ty * 16 + tx;
    const int lm = t >> 4;
    const int lk4 = (t & 15) * 4;
    const int m0 = blockIdx.x * 64;

    float4 bb = *reinterpret_cast<const float4*>(b1 + lk4);
#pragma unroll
    for (int i = 0; i < 4; i++) {
        int m = lm + 16 * i;
        int gm = m0 + m;
        float4 v = make_float4(0.f, 0.f, 0.f, 0.f);
        if (gm < N) {
            float di = g_dinv[gm];
            float4 a = *reinterpret_cast<const float4*>(&g_acc1[(size_t)gm * H + lk4]);
            v.x = fmaxf(a.x * di + bb.x, 0.f);
            v.y = fmaxf(a.y * di + bb.y, 0.f);
            v.z = fmaxf(a.z * di + bb.z, 0.f);
            v.w = fmaxf(a.w * di + bb.w, 0.f);
        }
        *reinterpret_cast<float4*>(&As[m][lk4]) = v;
        int k = lm + 16 * i;
        float4 w = *reinterpret_cast<const float4*>(W2 + (size_t)k * H + lk4);
        *reinterpret_cast<float4*>(&Ws[k][lk4]) = w;
    }
    __syncthreads();

    float acc[4][4];
#pragma unroll
    for (int i = 0; i < 4; i++)
#pragma unroll
        for (int j = 0; j < 4; j++) acc[i][j] = 0.f;

#pragma unroll 8
    for (int kk = 0; kk < 64; kk++) {
        float4 b4 = *reinterpret_cast<const float4*>(&Ws[kk][tx * 4]);
        float a0 = As[ty * 4 + 0][kk];
        float a1 = As[ty * 4 + 1][kk];
        float a2 = As[ty * 4 + 2][kk];
        float a3 = As[ty * 4 + 3][kk];
        acc[0][0] += a0 * b4.x; acc[0][1] += a0 * b4.y; acc[0][2] += a0 * b4.z; acc[0][3] += a0 * b4.w;
        acc[1][0] += a1 * b4.x; acc[1][1] += a1 * b4.y; acc[1][2] += a1 * b4.z; acc[1][3] += a1 * b4.w;
        acc[2][0] += a2 * b4.x; acc[2][1] += a2 * b4.y; acc[2][2] += a2 * b4.z; acc[2][3] += a2 * b4.w;
        acc[3][0] += a3 * b4.x; acc[3][1] += a3 * b4.y; acc[3][2] += a3 * b4.z; acc[3][3] += a3 * b4.w;
    }

#pragma unroll
    for (int i = 0; i < 4; i++) {
        int gm = m0 + ty * 4 + i;
        if (gm < N) {
            float di = g_dinv[gm];
            float4 r = make_float4(acc[i][0] * di, acc[i][1] * di, acc[i][2] * di, acc[i][3] * di);
            *reinterpret_cast<float4*>(&g_hs2[(size_t)gm * H + tx * 4]) = r;
            *reinterpret_cast<float4*>(&g_acc2[(size_t)gm * H + tx * 4]) = r;
        }
    }
}

// node MLP precompute: h2 = relu(acc2*dinv + b2)
// half=0: g_A = h2 @ Wm1[0:64] + bm1 ; half=1: g_B = h2 @ Wm1[64:128]
__global__ __launch_bounds__(256) void gemm3_tiled(
    const float* __restrict__ Wm1, const float* __restrict__ b2,
    const float* __restrict__ bm1, int N) {
    __shared__ float As[64][68];
    __shared__ float Ws[64][68];
    const int tx = threadIdx.x, ty = threadIdx.y;
    const int t = ty * 16 + tx;
    const int lm = t >> 4;
    const int lk4 = (t & 15) * 4;
    const int m0 = blockIdx.x * 64;
    const int half = blockIdx.y;

    float4 bb = *reinterpret_cast<const float4*>(b2 + lk4);
#pragma unroll
    for (int i = 0; i < 4; i++) {
        int m = lm + 16 * i;
        int gm = m0 + m;
        float4 v = make_float4(0.f, 0.f, 0.f, 0.f);
        if (gm < N) {
            float di = g_dinv[gm];
            float4 a = *reinterpret_cast<const float4*>(&g_acc2[(size_t)gm * H + lk4]);
            v.x = fmaxf(a.x * di + bb.x, 0.f);
            v.y = fmaxf(a.y * di + bb.y, 0.f);
            v.z = fmaxf(a.z * di + bb.z, 0.f);
            v.w = fmaxf(a.w * di + bb.w, 0.f);
        }
        *reinterpret_cast<float4*>(&As[m][lk4]) = v;
        int k = lm + 16 * i;
        float4 w = *reinterpret_cast<const float4*>(Wm1 + (size_t)(half * H + k) * H + lk4);
        *reinterpret_cast<float4*>(&Ws[k][lk4]) = w;
    }
    __syncthreads();

    float acc[4][4];
#pragma unroll
    for (int i = 0; i < 4; i++)
#pragma unroll
        for (int j = 0; j < 4; j++) acc[i][j] = 0.f;

#pragma unroll 8
    for (int kk = 0; kk < 64; kk++) {
        float4 b4 = *reinterpret_cast<const float4*>(&Ws[kk][tx * 4]);
        float a0 = As[ty * 4 + 0][kk];
        float a1 = As[ty * 4 + 1][kk];
        float a2 = As[ty * 4 + 2][kk];
        float a3 = As[ty * 4 + 3][kk];
        acc[0][0] += a0 * b4.x; acc[0][1] += a0 * b4.y; acc[0][2] += a0 * b4.z; acc[0][3] += a0 * b4.w;
        acc[1][0] += a1 * b4.x; acc[1][1] += a1 * b4.y; acc[1][2] += a1 * b4.z; acc[1][3] += a1 * b4.w;
        acc[2][0] += a2 * b4.x; acc[2][1] += a2 * b4.y; acc[2][2] += a2 * b4.z; acc[2][3] += a2 * b4.w;
        acc[3][0] += a3 * b4.x; acc[3][1] += a3 * b4.y; acc[3][2] += a3 * b4.z; acc[3][3] += a3 * b4.w;
    }

    float4 badd = make_float4(0.f, 0.f, 0.f, 0.f);
    if (half == 0) badd = *reinterpret_cast<const float4*>(bm1 + tx * 4);
    float* outbuf = (half == 0) ? g_A : g_B;
#pragma unroll
    for (int i = 0; i < 4; i++) {
        int gm = m0 + ty * 4 + i;
        if (gm < N) {
            float4 r = make_float4(acc[i][0] + badd.x, acc[i][1] + badd.y,
                                   acc[i][2] + badd.z, acc[i][3] + badd.w);
            *reinterpret_cast<float4*>(&outbuf[(size_t)gm * H + tx * 4]) = r;
        }
    }
}

// ---------------- scatter: acc[dst] += hs[src]  (16 threads/edge, red.v4)
__global__ void scatter_kernel(const int* __restrict__ src, const int* __restrict__ dst,
                               const float* __restrict__ hs, float* __restrict__ acc, int E) {
    int t = blockIdx.x * blockDim.x + threadIdx.x;
    int e = t >> 4;
    if (e >= E) return;
    int c = (t & 15) << 2;
    int s = src[e], d = dst[e];
    float4 v = *reinterpret_cast<const float4*>(hs + (size_t)s * H + c);
    float* p = acc + (size_t)d * H + c;
    asm volatile("red.global.add.v4.f32 [%0], {%1, %2, %3, %4};"
                 :: "l"(p), "f"(v.x), "f"(v.y), "f"(v.z), "f"(v.w) : "memory");
}

// ---------------- edge MLP: out[e] = relu(A[src]+B[dst]) @ Wm2 + bm2
// f32x2 compute, identical memory layout / LDS pattern to the R2 version.
__global__ void edge_kernel(const int* __restrict__ src, const int* __restrict__ dst,
                            const float* __restrict__ Wm2, const float* __restrict__ bm2,
                            float* __restrict__ out, int E) {
    __shared__ float Ws[H * C_OUT];   // [k][c] row-major, 16 floats per k
    __shared__ float bs[C_OUT];
    int tid = threadIdx.x;
    for (int i = tid; i < H * C_OUT; i += blockDim.x) Ws[i] = Wm2[i];
    if (tid < C_OUT) bs[tid] = bm2[tid];
    __syncthreads();

    int e = blockIdx.x * blockDim.x + tid;
    if (e >= E) return;
    int s = src[e], d = dst[e];
    const float4* Ap = reinterpret_cast<const float4*>(g_A + (size_t)s * H);
    const float4* Bp = reinterpret_cast<const float4*>(g_B + (size_t)d * H);

    // 16 output cols as 8 packed pairs
    ull acc2[8];
#pragma unroll
    for (int j = 0; j < 8; j++) acc2[j] = pk2(bs[2 * j], bs[2 * j + 1]);

#pragma unroll
    for (int q = 0; q < H / 4; q++) {
        float4 a4 = Ap[q];
        float4 b4 = Bp[q];
        ull zp[4];
        zp[0] = pk2(fmaxf(a4.x + b4.x, 0.f), fmaxf(a4.x + b4.x, 0.f));
        zp[1] = pk2(fmaxf(a4.y + b4.y, 0.f), fmaxf(a4.y + b4.y, 0.f));
        zp[2] = pk2(fmaxf(a4.z + b4.z, 0.f), fmaxf(a4.z + b4.z, 0.f));
        zp[3] = pk2(fmaxf(a4.w + b4.w, 0.f), fmaxf(a4.w + b4.w, 0.f));
#pragma unroll
        for (int kk = 0; kk < 4; kk++) {
            const ulonglong2* wrow = reinterpret_cast<const ulonglong2*>(Ws + (q * 4 + kk) * C_OUT);
#pragma unroll
            for (int j = 0; j < 4; j++) {
                ulonglong2 w2 = wrow[j];           // cols 4j..4j+3 as 2 pairs
                ffma2(acc2[2 * j + 0], zp[kk], w2.x);
                ffma2(acc2[2 * j + 1], zp[kk], w2.y);
            }
        }
    }

    float4* op = reinterpret_cast<float4*>(out + (size_t)e * C_OUT);
#pragma unroll
    for (int c = 0; c < 4; c++) {
        float2 p0 = unpk(acc2[2 * c + 0]);
        float2 p1 = unpk(acc2[2 * c + 1]);
        op[c] = make_float4(p0.x, p0.y, p1.x, p1.y);
    }
}

extern "C" void kernel_launch(void* const* d_in, const int* in_sizes, int n_in,
                              void* d_out, int out_size) {
    const float* x    = (const float*)d_in[0];
    const int*   ei   = (const int*)d_in[1];
    const float* W1   = (const float*)d_in[2];
    const float* b1   = (const float*)d_in[3];
    const float* W2   = (const float*)d_in[4];
    const float* b2   = (const float*)d_in[5];
    const float* Wm1  = (const float*)d_in[6];
    const float* bm1  = (const float*)d_in[7];
    const float* Wm2  = (const float*)d_in[8];
    const float* bm2  = (const float*)d_in[9];
    float* out = (float*)d_out;

    int N = in_sizes[0] / IN_F;
    int E = in_sizes[1] / 2;
    const int* src = ei;
    const int* dst = ei + E;

    int*   degi; cudaGetSymbolAddress((void**)&degi, g_degi);
    float* hs1;  cudaGetSymbolAddress((void**)&hs1,  g_hs1);
    float* acc1; cudaGetSymbolAddress((void**)&acc1, g_acc1);
    float* hs2;  cudaGetSymbolAddress((void**)&hs2,  g_hs2);
    float* acc2; cudaGetSymbolAddress((void**)&acc2, g_acc2);

    int blocks_m = (N + 63) / 64;

    // degrees
    cudaMemsetAsync(degi, 0, (size_t)N * sizeof(int));
    count_kernel<<<(E + 255) / 256, 256>>>(dst, E);

    // conv1 (dinv computed + persisted in epilogue)
    gemm1_tiled<<<blocks_m, dim3(16, 16)>>>(x, W1, N);
    {
        long long tot = (long long)E * 16;
        scatter_kernel<<<(int)((tot + 255) / 256), 256>>>(src, dst, hs1, acc1, E);
    }

    // conv2
    gemm2_tiled<<<blocks_m, dim3(16, 16)>>>(W2, b1, N);
    {
        long long tot = (long long)E * 16;
        scatter_kernel<<<(int)((tot + 255) / 256), 256>>>(src, dst, hs2, acc2, E);
    }

    // node-side MLP precompute
    gemm3_tiled<<<dim3(blocks_m, 2), dim3(16, 16)>>>(Wm1, b2, bm1, N);

    // edge MLP
    edge_kernel<<<(E + 255) / 256, 256>>>(src, dst, Wm2, bm2, out, E);
}

// round 8
// speedup vs baseline: 1.2479x; 1.1253x over previous
#include <cuda_runtime.h>
#include <cuda_bf16.h>
#include <cstdint>

// Problem constants (dataset fixed: N=50000, E=800000, IN=128, H=64, C=16)
#define MAXN 50016
#define MAXE 800000
#define H 64
#define IN_F 128
#define C_OUT 16

// Scratch (device globals; 16B aligned)
__device__ __align__(16) int   g_degi[MAXN];
__device__ __align__(16) int   g_fill[MAXN];
__device__ __align__(16) int   g_rowptr[MAXN];
__device__ __align__(16) int   g_cursor[4];
__device__ __align__(16) int   g_col[MAXE];
__device__ __align__(16) float g_dinv[MAXN];
__device__ __align__(16) float g_hs1[MAXN * H];
__device__ __align__(16) float g_acc1[MAXN * H];
__device__ __align__(16) float g_hs2[MAXN * H];
__device__ __align__(16) float g_acc2[MAXN * H];
__device__ __align__(16) float g_A[MAXN * H];
__device__ __align__(16) float g_B[MAXN * H];

typedef unsigned long long ull;

__device__ __forceinline__ void ffma2(ull& acc, ull a, ull b) {
    asm("fma.rn.f32x2 %0, %1, %2, %0;" : "+l"(acc) : "l"(a), "l"(b));
}
__device__ __forceinline__ ull pk2(float a, float b) {
    ull r;
    asm("mov.b64 %0, {%1, %2};" : "=l"(r) : "f"(a), "f"(b));
    return r;
}
__device__ __forceinline__ float2 unpk(ull v) {
    float2 r;
    asm("mov.b64 {%0, %1}, %2;" : "=f"(r.x), "=f"(r.y) : "l"(v));
    return r;
}

// ---------------- CSR build ----------------
__global__ void count_kernel(const int* __restrict__ dst, int E) {
    int e = blockIdx.x * blockDim.x + threadIdx.x;
    if (e < E) atomicAdd(&g_degi[dst[e]], 1);
}

// assign CSR segment starts via a global cursor (no scan needed;
// placement order is run-varying but numerically equivalent)
__global__ void assign_kernel(int N) {
    int n = blockIdx.x * blockDim.x + threadIdx.x;
    if (n < N) {
        int deg = g_degi[n];
        g_rowptr[n] = atomicAdd(&g_cursor[0], deg);
    }
}

__global__ void fill_kernel(const int* __restrict__ src, const int* __restrict__ dst, int E) {
    int e = blockIdx.x * blockDim.x + threadIdx.x;
    if (e >= E) return;
    int d = dst[e];
    int pos = g_rowptr[d] + atomicAdd(&g_fill[d], 1);
    g_col[pos] = src[e];
}

// ---------------- gather: out[n] = hs[n] + sum_{s in row(n)} hs[s]
// 16 threads/node (float4 chunk each), MLP=4 unrolled inner loop.
__global__ void gather_kernel(const float* __restrict__ hs, float* __restrict__ out, int N) {
    int t = blockIdx.x * blockDim.x + threadIdx.x;
    int n = t >> 4;
    if (n >= N) return;
    int c = (t & 15) << 2;
    const float* hp = hs + c;
    float4 acc = *reinterpret_cast<const float4*>(hp + (size_t)n * H);  // self loop
    int i = g_rowptr[n];
    int end = i + g_degi[n];
    for (; i + 4 <= end; i += 4) {
        int s0 = __ldg(&g_col[i + 0]);
        int s1 = __ldg(&g_col[i + 1]);
        int s2 = __ldg(&g_col[i + 2]);
        int s3 = __ldg(&g_col[i + 3]);
        float4 v0 = *reinterpret_cast<const float4*>(hp + (size_t)s0 * H);
        float4 v1 = *reinterpret_cast<const float4*>(hp + (size_t)s1 * H);
        float4 v2 = *reinterpret_cast<const float4*>(hp + (size_t)s2 * H);
        float4 v3 = *reinterpret_cast<const float4*>(hp + (size_t)s3 * H);
        acc.x += (v0.x + v1.x) + (v2.x + v3.x);
        acc.y += (v0.y + v1.y) + (v2.y + v3.y);
        acc.z += (v0.z + v1.z) + (v2.z + v3.z);
        acc.w += (v0.w + v1.w) + (v2.w + v3.w);
    }
    for (; i < end; i++) {
        int s = __ldg(&g_col[i]);
        float4 v = *reinterpret_cast<const float4*>(hp + (size_t)s * H);
        acc.x += v.x; acc.y += v.y; acc.z += v.z; acc.w += v.w;
    }
    *reinterpret_cast<float4*>(out + (size_t)n * H + c) = acc;
}

// =====================================================================
// Tiled GEMM kernels (proven form): M=64, N=64, 256 thr, 4x4 microtile
// =====================================================================

// conv1: hs1 = (x @ W1) * dinv ; writes g_dinv
__global__ __launch_bounds__(256) void gemm1_tiled(
    const float* __restrict__ x, const float* __restrict__ W1, int N) {
    __shared__ float As[64][68];
    __shared__ float Ws[64][68];
    const int tx = threadIdx.x, ty = threadIdx.y;
    const int t = ty * 16 + tx;
    const int lm = t >> 4;
    const int lk4 = (t & 15) * 4;
    const int m0 = blockIdx.x * 64;

    float acc[4][4];
#pragma unroll
    for (int i = 0; i < 4; i++)
#pragma unroll
        for (int j = 0; j < 4; j++) acc[i][j] = 0.f;

    for (int k0 = 0; k0 < IN_F; k0 += 64) {
        __syncthreads();
#pragma unroll
        for (int i = 0; i < 4; i++) {
            int m = lm + 16 * i;
            int gm = m0 + m;
            float4 v = make_float4(0.f, 0.f, 0.f, 0.f);
            if (gm < N) v = *reinterpret_cast<const float4*>(x + (size_t)gm * IN_F + k0 + lk4);
            *reinterpret_cast<float4*>(&As[m][lk4]) = v;
            int k = lm + 16 * i;
            float4 w = *reinterpret_cast<const float4*>(W1 + (size_t)(k0 + k) * H + lk4);
            *reinterpret_cast<float4*>(&Ws[k][lk4]) = w;
        }
        __syncthreads();
#pragma unroll 8
        for (int kk = 0; kk < 64; kk++) {
            float4 b4 = *reinterpret_cast<const float4*>(&Ws[kk][tx * 4]);
            float a0 = As[ty * 4 + 0][kk];
            float a1 = As[ty * 4 + 1][kk];
            float a2 = As[ty * 4 + 2][kk];
            float a3 = As[ty * 4 + 3][kk];
            acc[0][0] += a0 * b4.x; acc[0][1] += a0 * b4.y; acc[0][2] += a0 * b4.z; acc[0][3] += a0 * b4.w;
            acc[1][0] += a1 * b4.x; acc[1][1] += a1 * b4.y; acc[1][2] += a1 * b4.z; acc[1][3] += a1 * b4.w;
            acc[2][0] += a2 * b4.x; acc[2][1] += a2 * b4.y; acc[2][2] += a2 * b4.z; acc[2][3] += a2 * b4.w;
            acc[3][0] += a3 * b4.x; acc[3][1] += a3 * b4.y; acc[3][2] += a3 * b4.z; acc[3][3] += a3 * b4.w;
        }
    }

#pragma unroll
    for (int i = 0; i < 4; i++) {
        int gm = m0 + ty * 4 + i;
        if (gm < N) {
            float di = rsqrtf((float)(g_degi[gm] + 1));  // +1 self loop
            if (tx == 0) g_dinv[gm] = di;
            float4 r = make_float4(acc[i][0] * di, acc[i][1] * di, acc[i][2] * di, acc[i][3] * di);
            *reinterpret_cast<float4*>(&g_hs1[(size_t)gm * H + tx * 4]) = r;
        }
    }
}

// conv2: h1 = relu(acc1*dinv + b1); hs2 = (h1 @ W2) * dinv  (K=64)
__global__ __launch_bounds__(256) void gemm2_tiled(
    const float* __restrict__ W2, const float* __restrict__ b1, int N) {
    __shared__ float As[64][68];
    __shared__ float Ws[64][68];
    const int tx = threadIdx.x, ty = threadIdx.y;
    const int t = ty * 16 + tx;
    const int lm = t >> 4;
    const int lk4 = (t & 15) * 4;
    const int m0 = blockIdx.x * 64;

    float4 bb = *reinterpret_cast<const float4*>(b1 + lk4);
#pragma unroll
    for (int i = 0; i < 4; i++) {
        int m = lm + 16 * i;
        int gm = m0 + m;
        float4 v = make_float4(0.f, 0.f, 0.f, 0.f);
        if (gm < N) {
            float di = g_dinv[gm];
            float4 a = *reinterpret_cast<const float4*>(&g_acc1[(size_t)gm * H + lk4]);
            v.x = fmaxf(a.x * di + bb.x, 0.f);
            v.y = fmaxf(a.y * di + bb.y, 0.f);
            v.z = fmaxf(a.z * di + bb.z, 0.f);
            v.w = fmaxf(a.w * di + bb.w, 0.f);
        }
        *reinterpret_cast<float4*>(&As[m][lk4]) = v;
        int k = lm + 16 * i;
        float4 w = *reinterpret_cast<const float4*>(W2 + (size_t)k * H + lk4);
        *reinterpret_cast<float4*>(&Ws[k][lk4]) = w;
    }
    __syncthreads();

    float acc[4][4];
#pragma unroll
    for (int i = 0; i < 4; i++)
#pragma unroll
        for (int j = 0; j < 4; j++) acc[i][j] = 0.f;

#pragma unroll 8
    for (int kk = 0; kk < 64; kk++) {
        float4 b4 = *reinterpret_cast<const float4*>(&Ws[kk][tx * 4]);
        float a0 = As[ty * 4 + 0][kk];
        float a1 = As[ty * 4 + 1][kk];
        float a2 = As[ty * 4 + 2][kk];
        float a3 = As[ty * 4 + 3][kk];
        acc[0][0] += a0 * b4.x; acc[0][1] += a0 * b4.y; acc[0][2] += a0 * b4.z; acc[0][3] += a0 * b4.w;
        acc[1][0] += a1 * b4.x; acc[1][1] += a1 * b4.y; acc[1][2] += a1 * b4.z; acc[1][3] += a1 * b4.w;
        acc[2][0] += a2 * b4.x; acc[2][1] += a2 * b4.y; acc[2][2] += a2 * b4.z; acc[2][3] += a2 * b4.w;
        acc[3][0] += a3 * b4.x; acc[3][1] += a3 * b4.y; acc[3][2] += a3 * b4.z; acc[3][3] += a3 * b4.w;
    }

#pragma unroll
    for (int i = 0; i < 4; i++) {
        int gm = m0 + ty * 4 + i;
        if (gm < N) {
            float di = g_dinv[gm];
            float4 r = make_float4(acc[i][0] * di, acc[i][1] * di, acc[i][2] * di, acc[i][3] * di);
            *reinterpret_cast<float4*>(&g_hs2[(size_t)gm * H + tx * 4]) = r;
        }
    }
}

// node MLP precompute: h2 = relu(acc2*dinv + b2)
// half=0: g_A = h2 @ Wm1[0:64] + bm1 ; half=1: g_B = h2 @ Wm1[64:128]
__global__ __launch_bounds__(256) void gemm3_tiled(
    const float* __restrict__ Wm1, const float* __restrict__ b2,
    const float* __restrict__ bm1, int N) {
    __shared__ float As[64][68];
    __shared__ float Ws[64][68];
    const int tx = threadIdx.x, ty = threadIdx.y;
    const int t = ty * 16 + tx;
    const int lm = t >> 4;
    const int lk4 = (t & 15) * 4;
    const int m0 = blockIdx.x * 64;
    const int half = blockIdx.y;

    float4 bb = *reinterpret_cast<const float4*>(b2 + lk4);
#pragma unroll
    for (int i = 0; i < 4; i++) {
        int m = lm + 16 * i;
        int gm = m0 + m;
        float4 v = make_float4(0.f, 0.f, 0.f, 0.f);
        if (gm < N) {
            float di = g_dinv[gm];
            float4 a = *reinterpret_cast<const float4*>(&g_acc2[(size_t)gm * H + lk4]);
            v.x = fmaxf(a.x * di + bb.x, 0.f);
            v.y = fmaxf(a.y * di + bb.y, 0.f);
            v.z = fmaxf(a.z * di + bb.z, 0.f);
            v.w = fmaxf(a.w * di + bb.w, 0.f);
        }
        *reinterpret_cast<float4*>(&As[m][lk4]) = v;
        int k = lm + 16 * i;
        float4 w = *reinterpret_cast<const float4*>(Wm1 + (size_t)(half * H + k) * H + lk4);
        *reinterpret_cast<float4*>(&Ws[k][lk4]) = w;
    }
    __syncthreads();

    float acc[4][4];
#pragma unroll
    for (int i = 0; i < 4; i++)
#pragma unroll
        for (int j = 0; j < 4; j++) acc[i][j] = 0.f;

#pragma unroll 8
    for (int kk = 0; kk < 64; kk++) {
        float4 b4 = *reinterpret_cast<const float4*>(&Ws[kk][tx * 4]);
        float a0 = As[ty * 4 + 0][kk];
        float a1 = As[ty * 4 + 1][kk];
        float a2 = As[ty * 4 + 2][kk];
        float a3 = As[ty * 4 + 3][kk];
        acc[0][0] += a0 * b4.x; acc[0][1] += a0 * b4.y; acc[0][2] += a0 * b4.z; acc[0][3] += a0 * b4.w;
        acc[1][0] += a1 * b4.x; acc[1][1] += a1 * b4.y; acc[1][2] += a1 * b4.z; acc[1][3] += a1 * b4.w;
        acc[2][0] += a2 * b4.x; acc[2][1] += a2 * b4.y; acc[2][2] += a2 * b4.z; acc[2][3] += a2 * b4.w;
        acc[3][0] += a3 * b4.x; acc[3][1] += a3 * b4.y; acc[3][2] += a3 * b4.z; acc[3][3] += a3 * b4.w;
    }

    float4 badd = make_float4(0.f, 0.f, 0.f, 0.f);
    if (half == 0) badd = *reinterpret_cast<const float4*>(bm1 + tx * 4);
    float* outbuf = (half == 0) ? g_A : g_B;
#pragma unroll
    for (int i = 0; i < 4; i++) {
        int gm = m0 + ty * 4 + i;
        if (gm < N) {
            float4 r = make_float4(acc[i][0] + badd.x, acc[i][1] + badd.y,
                                   acc[i][2] + badd.z, acc[i][3] + badd.w);
            *reinterpret_cast<float4*>(&outbuf[(size_t)gm * H + tx * 4]) = r;
        }
    }
}

// ---------------- edge MLP: out[e] = relu(A[src]+B[dst]) @ Wm2 + bm2 (f32x2)
__global__ void edge_kernel(const int* __restrict__ src, const int* __restrict__ dst,
                            const float* __restrict__ Wm2, const float* __restrict__ bm2,
                            float* __restrict__ out, int E) {
    __shared__ float Ws[H * C_OUT];
    __shared__ float bs[C_OUT];
    int tid = threadIdx.x;
    for (int i = tid; i < H * C_OUT; i += blockDim.x) Ws[i] = Wm2[i];
    if (tid < C_OUT) bs[tid] = bm2[tid];
    __syncthreads();

    int e = blockIdx.x * blockDim.x + tid;
    if (e >= E) return;
    int s = src[e], d = dst[e];
    const float4* Ap = reinterpret_cast<const float4*>(g_A + (size_t)s * H);
    const float4* Bp = reinterpret_cast<const float4*>(g_B + (size_t)d * H);

    ull acc2[8];
#pragma unroll
    for (int j = 0; j < 8; j++) acc2[j] = pk2(bs[2 * j], bs[2 * j + 1]);

#pragma unroll
    for (int q = 0; q < H / 4; q++) {
        float4 a4 = Ap[q];
        float4 b4 = Bp[q];
        ull zp[4];
        zp[0] = pk2(fmaxf(a4.x + b4.x, 0.f), fmaxf(a4.x + b4.x, 0.f));
        zp[1] = pk2(fmaxf(a4.y + b4.y, 0.f), fmaxf(a4.y + b4.y, 0.f));
        zp[2] = pk2(fmaxf(a4.z + b4.z, 0.f), fmaxf(a4.z + b4.z, 0.f));
        zp[3] = pk2(fmaxf(a4.w + b4.w, 0.f), fmaxf(a4.w + b4.w, 0.f));
#pragma unroll
        for (int kk = 0; kk < 4; kk++) {
            const ulonglong2* wrow = reinterpret_cast<const ulonglong2*>(Ws + (q * 4 + kk) * C_OUT);
#pragma unroll
            for (int j = 0; j < 4; j++) {
                ulonglong2 w2 = wrow[j];
                ffma2(acc2[2 * j + 0], zp[kk], w2.x);
                ffma2(acc2[2 * j + 1], zp[kk], w2.y);
            }
        }
    }

    float4* op = reinterpret_cast<float4*>(out + (size_t)e * C_OUT);
#pragma unroll
    for (int c = 0; c < 4; c++) {
        float2 p0 = unpk(acc2[2 * c + 0]);
        float2 p1 = unpk(acc2[2 * c + 1]);
        op[c] = make_float4(p0.x, p0.y, p1.x, p1.y);
    }
}

extern "C" void kernel_launch(void* const* d_in, const int* in_sizes, int n_in,
                              void* d_out, int out_size) {
    const float* x    = (const float*)d_in[0];
    const int*   ei   = (const int*)d_in[1];
    const float* W1   = (const float*)d_in[2];
    const float* b1   = (const float*)d_in[3];
    const float* W2   = (const float*)d_in[4];
    const float* b2   = (const float*)d_in[5];
    const float* Wm1  = (const float*)d_in[6];
    const float* bm1  = (const float*)d_in[7];
    const float* Wm2  = (const float*)d_in[8];
    const float* bm2  = (const float*)d_in[9];
    float* out = (float*)d_out;

    int N = in_sizes[0] / IN_F;
    int E = in_sizes[1] / 2;
    const int* src = ei;
    const int* dst = ei + E;

    int*   degi;   cudaGetSymbolAddress((void**)&degi,   g_degi);
    int*   fill;   cudaGetSymbolAddress((void**)&fill,   g_fill);
    int*   cursor; cudaGetSymbolAddress((void**)&cursor, g_cursor);
    float* hs1;  cudaGetSymbolAddress((void**)&hs1,  g_hs1);
    float* acc1; cudaGetSymbolAddress((void**)&acc1, g_acc1);
    float* hs2;  cudaGetSymbolAddress((void**)&hs2,  g_hs2);
    float* acc2; cudaGetSymbolAddress((void**)&acc2, g_acc2);

    int blocks_m = (N + 63) / 64;

    // CSR build (by destination), no scan: cursor-assigned segments
    cudaMemsetAsync(degi, 0, (size_t)N * sizeof(int));
    cudaMemsetAsync(fill, 0, (size_t)N * sizeof(int));
    cudaMemsetAsync(cursor, 0, 4 * sizeof(int));
    count_kernel<<<(E + 255) / 256, 256>>>(dst, E);
    assign_kernel<<<(N + 255) / 256, 256>>>(N);
    fill_kernel<<<(E + 255) / 256, 256>>>(src, dst, E);

    // conv1
    gemm1_tiled<<<blocks_m, dim3(16, 16)>>>(x, W1, N);
    gather_kernel<<<(N * 16 + 255) / 256, 256>>>(hs1, acc1, N);

    // conv2
    gemm2_tiled<<<blocks_m, dim3(16, 16)>>>(W2, b1, N);
    gather_kernel<<<(N * 16 + 255) / 256, 256>>>(hs2, acc2, N);

    // node-side MLP precompute
    gemm3_tiled<<<dim3(blocks_m, 2), dim3(16, 16)>>>(Wm1, b2, bm1, N);

    // edge MLP
    edge_kernel<<<(E + 255) / 256, 256>>>(src, dst, Wm2, bm2, out, E);
}